// round 15
// baseline (speedup 1.0000x reference)
#include <cuda_runtime.h>
#include <cuda_fp16.h>
#include <mma.h>

using namespace nvcuda;

// ---------------------------------------------------------------------------
// GraphEncoder: fp16 TC GEMMs (128x256 CTA, full-width tiles) + flash attn.
// Shapes: B=16, S=1024 (segments 512/256/256), H=256, heads=4 (Dh=64), F=400.
// ---------------------------------------------------------------------------

#define NB 16
#define SEQ 1024
#define HID 256
#define NHEADS 4
#define DH 64
#define FFP 512
#define TOKENS (NB * SEQ)

// -------------------- scratch (device globals; no allocation) --------------
__device__ __half g_hth[NB * SEQ * SEQ];
__device__ __half g_h0h[TOKENS * HID];
__device__ __half g_th[TOKENS * HID];
__device__ __half g_xh[TOKENS * HID];
__device__ float  g_x32[TOKENS * HID];
__device__ __half g_x1h[TOKENS * HID];
__device__ float  g_x132[TOKENS * HID];
__device__ __half g_qkvh[TOKENS * 3 * HID];
__device__ __half g_ctxh[TOKENS * HID];
__device__ __half g_ffh[TOKENS * FFP];
__device__ float  g_mean[NB * 3 * HID];
__device__ __half g_wg1h[HID * HID];
__device__ __half g_wg2h[HID * HID];
__device__ __half g_wqkvh[HID * 3 * HID];
__device__ __half g_woh[HID * HID];
__device__ __half g_w1ph[HID * FFP];
__device__ float  g_b1p[FFP];
__device__ __half g_w2ph[FFP * HID];
__device__ int    g_rowtab[256];

__device__ __forceinline__ unsigned sptr(const void* p) {
    return (unsigned)__cvta_generic_to_shared(p);
}
#define CPA16(dst, src) asm volatile("cp.async.ca.shared.global [%0], [%1], 16;" :: "r"(dst), "l"(src))
#define CPA_COMMIT()    asm volatile("cp.async.commit_group;")
#define CPA_WAIT0()     asm volatile("cp.async.wait_group 0;")
#define CPA_WAIT1()     asm volatile("cp.async.wait_group 1;")

// FMA-pipe exp2 (no MUFU)
__device__ __forceinline__ float fexp2(float y) {
    y = fmaxf(y, -80.f);
    float t = y + 12582912.f;
    int   n = __float_as_int(t) - 0x4B400000;
    float f = y - (t - 12582912.f);
    float p = 1.f + f * (0.69314718f + f * (0.24022651f +
                   f * (0.05550411f + f * 0.00961813f)));
    return __int_as_float(__float_as_int(p) + (n << 23));
}
#define SM_SCALE 0.18033688f   // 0.125 * log2(e)

// -------------------- probe: fp32 acc element->row map ---------------------
__global__ void probe_k(int* __restrict__ rowtab)
{
    __shared__ float pat[16 * 16];
    int lane = threadIdx.x;
    wmma::fragment<wmma::accumulator, 16, 16, 16, float> fr;
    for (int i = lane; i < 256; i += 32) pat[i] = (float)(i >> 4);
    __syncwarp();
    wmma::load_matrix_sync(fr, pat, 16, wmma::mem_row_major);
#pragma unroll
    for (int e = 0; e < 8; e++) rowtab[lane * 8 + e] = (int)fr.x[e];
}

// -------------------- prep kernels -----------------------------------------
__global__ void cvt4_k(const float4* __restrict__ in, __half2* __restrict__ out, int n4)
{
    int i = blockIdx.x * 256 + threadIdx.x;
    if (i < n4) {
        float4 v = in[i];
        out[i * 2]     = __floats2half2_rn(v.x, v.y);
        out[i * 2 + 1] = __floats2half2_rn(v.z, v.w);
    }
}
__global__ void gather_h_k(const int* __restrict__ idx, const float* __restrict__ tab,
                           __half* __restrict__ out)
{
    long tok = blockIdx.x;
    int id = idx[tok];
    const float4 v = ((const float4*)(tab + (long)id * HID))[threadIdx.x];
    __half2* dst = (__half2*)(out + tok * HID) + threadIdx.x * 2;
    dst[0] = __floats2half2_rn(v.x, v.y);
    dst[1] = __floats2half2_rn(v.z, v.w);
}
__global__ void prep_w_k(
    const float* __restrict__ Wg1, const float* __restrict__ Wg2,
    const float* __restrict__ Wqkv, const float* __restrict__ Wo,
    const float* __restrict__ Wff1, const float* __restrict__ bff1,
    const float* __restrict__ Wff2,
    __half* __restrict__ wg1h, __half* __restrict__ wg2h,
    __half* __restrict__ wqkvh, __half* __restrict__ woh,
    __half* __restrict__ w1ph, float* __restrict__ b1p,
    __half* __restrict__ w2ph, float* __restrict__ mean)
{
    int i = blockIdx.x * 256 + threadIdx.x;
    if (i < 65536) { wg1h[i] = __float2half(Wg1[i]); return; }
    i -= 65536;
    if (i < 65536) { wg2h[i] = __float2half(Wg2[i]); return; }
    i -= 65536;
    if (i < 196608) { wqkvh[i] = __float2half(Wqkv[i]); return; }
    i -= 196608;
    if (i < 65536) { woh[i] = __float2half(Wo[i]); return; }
    i -= 65536;
    if (i < 131072) {
        int r = i >> 9, c = i & 511;
        w1ph[i] = __float2half((c < 400) ? Wff1[r * 400 + c] : 0.f);
        return;
    }
    i -= 131072;
    if (i < 131072) {
        int r = i >> 8, c = i & 255;
        w2ph[i] = __float2half((r < 400) ? Wff2[r * 256 + c] : 0.f);
        return;
    }
    i -= 131072;
    if (i < 512) { b1p[i] = (i < 400) ? bff1[i] : 0.f; return; }
    i -= 512;
    if (i < NB * 3 * HID) mean[i] = 0.f;
}

// -------------------- fp16 wide GEMM (128x256 CTA, 256 thr, BK=32) ---------
// C = A@B + bias (relu?). M%128==0, N%256==0, K%32==0.
#define BKH 32
#define WAPH 40
#define WBPH 264
#define WASH (128 * WAPH)               // 5120 halfs / stage
#define WBSH (BKH * WBPH)               // 8448 halfs / stage
#define WSTAGES 3
#define WEPLD 260
#define WPIPE_BYTES (WSTAGES * (WASH + WBSH) * 2)     // 81408
#define WEPI_BYTES (128 * WEPLD * 4)                  // 133120
#define GEMM_SMEM_BYTES (WEPI_BYTES)

__global__ void __launch_bounds__(256, 1) gemm_w_h(
    const __half* __restrict__ A, const __half* __restrict__ Bm,
    const float* __restrict__ bias, __half* __restrict__ C16,
    float* __restrict__ C32,
    int K, int lda, int ldb, int ldc,
    long sAb, long sBb, long sCb, int relu)
{
    extern __shared__ __half smh[];

    const int z = blockIdx.z;
    A  += (long)z * sAb;
    Bm += (long)z * sBb;

    const int tid = threadIdx.x;
    const int w = tid >> 5;
    const int wm = w & 1, wn = w >> 1;          // 2x4 warps, 64x64 tiles
    const int rowTile = blockIdx.y * 128;
    const int colTile = blockIdx.x * 256;

    auto loadA = [&](int kt, int s) {
        const __half* Ag = A + (long)rowTile * lda + kt * BKH;
        __half* sa = smh + s * WASH;
#pragma unroll
        for (int i = 0; i < 2; i++) {
            int idx = tid + i * 256;            // 512 chunks: 128 rows x 4
            int r = idx >> 2, c8 = (idx & 3) * 8;
            CPA16(sptr(sa + r * WAPH + c8), Ag + (long)r * lda + c8);
        }
    };
    auto loadB = [&](int kt, int s) {
        const __half* Bg = Bm + (long)(kt * BKH) * ldb + colTile;
        __half* sb = smh + WSTAGES * WASH + s * WBSH;
#pragma unroll
        for (int i = 0; i < 4; i++) {
            int idx = tid + i * 256;            // 1024 chunks: 32 rows x 32
            int r = idx >> 5, c8 = (idx & 31) * 8;
            CPA16(sptr(sb + r * WBPH + c8), Bg + (long)r * ldb + c8);
        }
    };

    loadA(0, 0); loadB(0, 0); CPA_COMMIT();
    loadA(1, 1); loadB(1, 1); CPA_COMMIT();

    wmma::fragment<wmma::accumulator, 16, 16, 16, float> acc[4][4];
#pragma unroll
    for (int mi = 0; mi < 4; mi++)
#pragma unroll
        for (int ni = 0; ni < 4; ni++) wmma::fill_fragment(acc[mi][ni], 0.f);

    const int nk = K / BKH;
    for (int kt = 0; kt < nk; kt++) {
        CPA_WAIT1();
        __syncthreads();
        if (kt + 2 < nk) { int s = (kt + 2) % WSTAGES; loadA(kt + 2, s); loadB(kt + 2, s); CPA_COMMIT(); }

        const __half* sa = smh + (kt % WSTAGES) * WASH;
        const __half* sb = smh + WSTAGES * WASH + (kt % WSTAGES) * WBSH;

#pragma unroll
        for (int ks = 0; ks < 2; ks++) {
            wmma::fragment<wmma::matrix_a, 16, 16, 16, __half, wmma::row_major> af[4];
#pragma unroll
            for (int mi = 0; mi < 4; mi++)
                wmma::load_matrix_sync(af[mi], sa + (wm * 64 + mi * 16) * WAPH + ks * 16, WAPH);
            wmma::fragment<wmma::matrix_b, 16, 16, 16, __half, wmma::row_major> bf[4];
#pragma unroll
            for (int ni = 0; ni < 4; ni++)
                wmma::load_matrix_sync(bf[ni], sb + (ks * 16) * WBPH + wn * 64 + ni * 16, WBPH);
#pragma unroll
            for (int mi = 0; mi < 4; mi++)
#pragma unroll
                for (int ni = 0; ni < 4; ni++)
                    wmma::mma_sync(acc[mi][ni], af[mi], bf[ni], acc[mi][ni]);
        }
    }
    CPA_WAIT0();
    __syncthreads();   // pipeline smem free -> fp32 epilogue tile

    float* epi = (float*)smh;
#pragma unroll
    for (int mi = 0; mi < 4; mi++)
#pragma unroll
        for (int ni = 0; ni < 4; ni++)
            wmma::store_matrix_sync(epi + (wm * 64 + mi * 16) * WEPLD + wn * 64 + ni * 16,
                                    acc[mi][ni], WEPLD, wmma::mem_row_major);
    __syncthreads();

    __half* C16z = C16 + (long)z * sCb;
    float*  C32z = C32 ? C32 + (long)z * sCb : nullptr;
#pragma unroll 4
    for (int i = 0; i < 64; i++) {
        int idx = tid + i * 256;                // 16384 pairs: 128 rows x 128
        int r = idx >> 7, c = (idx & 127) * 2;
        float v0 = epi[r * WEPLD + c];
        float v1 = epi[r * WEPLD + c + 1];
        if (bias) { v0 += bias[colTile + c]; v1 += bias[colTile + c + 1]; }
        if (relu) { v0 = fmaxf(v0, 0.f); v1 = fmaxf(v1, 0.f); }
        long off = (long)(rowTile + r) * ldc + colTile + c;
        *(__half2*)(C16z + off) = __floats2half2_rn(v0, v1);
        if (C32z) *(float2*)(C32z + off) = make_float2(v0, v1);
    }
}

// -------------------- fp16 GEMM + residual + LayerNorm (+ fused mean) ------
#define LSTAGES 3
#define LAPH 40
#define LBPH 264
#define LASH (128 * LAPH)
#define LBSH (BKH * LBPH)
#define LEPI_OFF (LSTAGES * (LASH + LBSH))
#define LBPADF 260
#define LN_SMEM_BYTES (LEPI_OFF * 2 + (128 * LBPADF + 2 * 128) * 4)

__global__ void __launch_bounds__(256, 1) gemm_ln_h(
    const __half* __restrict__ A, const __half* __restrict__ Bm,
    const float* __restrict__ bias, const float* __restrict__ res,
    const float* __restrict__ lng, const float* __restrict__ lnb,
    float* __restrict__ out32, __half* __restrict__ out16,
    float* __restrict__ meanout, int K, int lda)
{
    extern __shared__ __half smh[];
    float* epi = (float*)(smh + LEPI_OFF);
    float* smu = epi + 128 * LBPADF;
    float* srs = smu + 128;

    const int tid = threadIdx.x;
    const int w = tid >> 5;
    const int wm = w & 1, wn = w >> 1;
    const int rowTile = blockIdx.x * 128;

    auto loadA = [&](int kt, int s) {
        const __half* Ag = A + (long)rowTile * lda + kt * BKH;
        __half* sa = smh + s * LASH;
#pragma unroll
        for (int i = 0; i < 2; i++) {
            int idx = tid + i * 256;
            int r = idx >> 2, c8 = (idx & 3) * 8;
            CPA16(sptr(sa + r * LAPH + c8), Ag + (long)r * lda + c8);
        }
    };
    auto loadB = [&](int kt, int s) {
        const __half* Bg = Bm + (long)(kt * BKH) * 256;
        __half* sb = smh + LSTAGES * LASH + s * LBSH;
#pragma unroll
        for (int i = 0; i < 4; i++) {
            int idx = tid + i * 256;
            int r = idx >> 5, c8 = (idx & 31) * 8;
            CPA16(sptr(sb + r * LBPH + c8), Bg + (long)r * 256 + c8);
        }
    };

    loadA(0, 0); loadB(0, 0); CPA_COMMIT();
    loadA(1, 1); loadB(1, 1); CPA_COMMIT();

    wmma::fragment<wmma::accumulator, 16, 16, 16, float> acc[4][4];
#pragma unroll
    for (int mi = 0; mi < 4; mi++)
#pragma unroll
        for (int ni = 0; ni < 4; ni++) wmma::fill_fragment(acc[mi][ni], 0.f);

    const int nk = K / BKH;
    for (int kt = 0; kt < nk; kt++) {
        CPA_WAIT1();
        __syncthreads();
        if (kt + 2 < nk) { int s = (kt + 2) % LSTAGES; loadA(kt + 2, s); loadB(kt + 2, s); CPA_COMMIT(); }

        const __half* sa = smh + (kt % LSTAGES) * LASH;
        const __half* sb = smh + LSTAGES * LASH + (kt % LSTAGES) * LBSH;

#pragma unroll
        for (int ks = 0; ks < 2; ks++) {
            wmma::fragment<wmma::matrix_a, 16, 16, 16, __half, wmma::row_major> af[4];
#pragma unroll
            for (int mi = 0; mi < 4; mi++)
                wmma::load_matrix_sync(af[mi], sa + (wm * 64 + mi * 16) * LAPH + ks * 16, LAPH);
            wmma::fragment<wmma::matrix_b, 16, 16, 16, __half, wmma::row_major> bf[4];
#pragma unroll
            for (int ni = 0; ni < 4; ni++)
                wmma::load_matrix_sync(bf[ni], sb + (ks * 16) * LBPH + wn * 64 + ni * 16, LBPH);
#pragma unroll
            for (int mi = 0; mi < 4; mi++)
#pragma unroll
                for (int ni = 0; ni < 4; ni++)
                    wmma::mma_sync(acc[mi][ni], af[mi], bf[ni], acc[mi][ni]);
        }
    }
    __syncthreads();

#pragma unroll
    for (int mi = 0; mi < 4; mi++)
#pragma unroll
        for (int ni = 0; ni < 4; ni++)
            wmma::store_matrix_sync(epi + (wm * 64 + mi * 16) * LBPADF + wn * 64 + ni * 16,
                                    acc[mi][ni], LBPADF, wmma::mem_row_major);
    __syncthreads();

#pragma unroll 8
    for (int i = 0; i < 128; i++) {
        int idx = tid + i * 256;
        int r = idx >> 8, c = idx & 255;
        epi[r * LBPADF + c] += bias[c] + res[(long)(rowTile + r) * HID + c];
    }
    __syncthreads();

    {
        const int r = tid >> 1, hf = tid & 1;
        const float* row = epi + r * LBPADF + hf * 128;
        float s = 0.f, s2 = 0.f;
#pragma unroll 8
        for (int c = 0; c < 128; c++) { float v = row[c]; s += v; s2 += v * v; }
        s  += __shfl_xor_sync(0xffffffffu, s, 1);
        s2 += __shfl_xor_sync(0xffffffffu, s2, 1);
        if (hf == 0) {
            float mu = s * (1.f / 256.f);
            float var = s2 * (1.f / 256.f) - mu * mu;
            smu[r] = mu;
            srs[r] = rsqrtf(var + 1e-5f);
        }
    }
    __syncthreads();

    if (meanout) {
        int grow = rowTile;
        int b = grow >> 10, pos = grow & 1023;
        int sgi = (pos < 512) ? 0 : ((pos < 768) ? 1 : 2);
        int seg = b * 3 + sgi;
        const int c = tid;
        float s = 0.f;
#pragma unroll 8
        for (int r = 0; r < 128; r++)
            s += (epi[r * LBPADF + c] - smu[r]) * srs[r];
        atomicAdd(&meanout[(long)seg * HID + c], s * lng[c] + 128.f * lnb[c]);
    } else {
#pragma unroll 4
        for (int i = 0; i < 64; i++) {
            int idx = tid + i * 256;
            int r = idx >> 7, c = (idx & 127) * 2;
            float v0 = (epi[r * LBPADF + c]     - smu[r]) * srs[r] * lng[c]     + lnb[c];
            float v1 = (epi[r * LBPADF + c + 1] - smu[r]) * srs[r] * lng[c + 1] + lnb[c + 1];
            long off = (long)(rowTile + r) * HID + c;
            *(float2*)(out32 + off) = make_float2(v0, v1);
            if (out16) *(__half2*)(out16 + off) = __floats2half2_rn(v0, v1);
        }
    }
}

// -------------------- fp16 flash attention ---------------------------------
#define QLDH 72
#define SLDF 132
#define PLDH 136
#define FS_Q 0
#define FS_K (128 * QLDH)
#define FS_V (2 * 128 * QLDH)
#define FS_P (3 * 128 * QLDH)
#define FS_F 45056
#define FLASH_SMEM_BYTES (FS_F * 2 + (128 * SLDF + 3 * 128) * 4)

__global__ void __launch_bounds__(256) flash_k(
    const __half* __restrict__ qkv, __half* __restrict__ ctx,
    const int* __restrict__ rowtab)
{
    extern __shared__ __half smh[];
    __half* sQ = smh + FS_Q;
    __half* sK = smh + FS_K;
    __half* sV = smh + FS_V;
    __half* sP = smh + FS_P;
    float* sS = (float*)(smh + FS_F);
    float* al = sS + 128 * SLDF;
    float* mrow = al + 128;
    float* lrow = mrow + 128;

    const int bx = blockIdx.x;
    int segOff, L, qt;
    if (bx < 4)      { segOff = 0;   L = 512; qt = bx; }
    else if (bx < 6) { segOff = 512; L = 256; qt = bx - 4; }
    else             { segOff = 768; L = 256; qt = bx - 6; }

    const int bh = blockIdx.y;
    const int b = bh >> 2, h = bh & 3;
    const int tid = threadIdx.x;
    const int w = tid >> 5, lane = tid & 31;
    const int wm = w & 3, wn = w >> 2;

    const __half* base = qkv + ((long)b * SEQ + segOff) * 768 + h * 64;

    auto loadT = [&](const __half* g, __half* s) {
#pragma unroll
        for (int i = 0; i < 4; i++) {
            int idx = tid + i * 256;
            int r = idx >> 3, c8 = (idx & 7) * 8;
            CPA16(sptr(s + r * QLDH + c8), g + (long)r * 768 + c8);
        }
    };

    int rt[8];
#pragma unroll
    for (int e = 0; e < 8; e++) rt[e] = rowtab[lane * 8 + e];

    if (tid < 128) { mrow[tid] = -1e30f; lrow[tid] = 0.f; }

    loadT(base + (long)qt * 128 * 768, sQ);
    loadT(base + 256, sK); CPA_COMMIT();
    loadT(base + 512, sV); CPA_COMMIT();

    wmma::fragment<wmma::accumulator, 16, 16, 16, float> oacc[2][2];
#pragma unroll
    for (int mi = 0; mi < 2; mi++)
#pragma unroll
        for (int ni = 0; ni < 2; ni++) wmma::fill_fragment(oacc[mi][ni], 0.f);

    const int nt = L >> 7;
    for (int t = 0; t < nt; t++) {
        CPA_WAIT1();
        __syncthreads();

        {
            wmma::fragment<wmma::accumulator, 16, 16, 16, float> sacc[2][4];
#pragma unroll
            for (int mi = 0; mi < 2; mi++)
#pragma unroll
                for (int ni = 0; ni < 4; ni++) wmma::fill_fragment(sacc[mi][ni], 0.f);
#pragma unroll
            for (int k = 0; k < DH; k += 16) {
                wmma::fragment<wmma::matrix_a, 16, 16, 16, __half, wmma::row_major> af[2];
#pragma unroll
                for (int mi = 0; mi < 2; mi++)
                    wmma::load_matrix_sync(af[mi], sQ + (wm * 32 + mi * 16) * QLDH + k, QLDH);
                wmma::fragment<wmma::matrix_b, 16, 16, 16, __half, wmma::col_major> bf[4];
#pragma unroll
                for (int ni = 0; ni < 4; ni++)
                    wmma::load_matrix_sync(bf[ni], sK + (wn * 64 + ni * 16) * QLDH + k, QLDH);
#pragma unroll
                for (int mi = 0; mi < 2; mi++)
#pragma unroll
                    for (int ni = 0; ni < 4; ni++)
                        wmma::mma_sync(sacc[mi][ni], af[mi], bf[ni], sacc[mi][ni]);
            }
#pragma unroll
            for (int mi = 0; mi < 2; mi++)
#pragma unroll
                for (int ni = 0; ni < 4; ni++)
                    wmma::store_matrix_sync(sS + (wm * 32 + mi * 16) * SLDF + wn * 64 + ni * 16,
                                            sacc[mi][ni], SLDF, wmma::mem_row_major);
        }
        __syncthreads();

        if (t + 1 < nt) { loadT(base + 256 + (long)(t + 1) * 128 * 768, sK); CPA_COMMIT(); }

        {
            const int r = tid >> 1, hf = tid & 1;
            float* row = sS + r * SLDF + hf * 64;
            __half* prow = sP + r * PLDH + hf * 64;
            float mx = -1e30f;
#pragma unroll 8
            for (int c = 0; c < 64; c++) mx = fmaxf(mx, row[c]);
            mx = fmaxf(mx, __shfl_xor_sync(0xffffffffu, mx, 1));
            mx *= SM_SCALE;
            float m_old = mrow[r];
            float m_new = fmaxf(m_old, mx);
            float a = fexp2(m_old - m_new);
            float sum = 0.f;
#pragma unroll 4
            for (int c = 0; c < 64; c++) {
                float p = fexp2(row[c] * SM_SCALE - m_new);
                prow[c] = __float2half(p);
                sum += p;
            }
            sum += __shfl_xor_sync(0xffffffffu, sum, 1);
            if (hf == 0) {
                mrow[r] = m_new;
                lrow[r] = lrow[r] * a + sum;
                al[r] = a;
            }
        }
        if (t + 1 < nt) { CPA_WAIT1(); } else { CPA_WAIT0(); }
        __syncthreads();

        {
            float av[2][8];
#pragma unroll
            for (int mi = 0; mi < 2; mi++)
#pragma unroll
                for (int e = 0; e < 8; e++)
                    av[mi][e] = al[wm * 32 + mi * 16 + rt[e]];
#pragma unroll
            for (int mi = 0; mi < 2; mi++)
#pragma unroll
                for (int ni = 0; ni < 2; ni++)
#pragma unroll
                    for (int e = 0; e < 8; e++)
                        oacc[mi][ni].x[e] *= av[mi][e];

#pragma unroll
            for (int k = 0; k < 128; k += 16) {
                wmma::fragment<wmma::matrix_a, 16, 16, 16, __half, wmma::row_major> af[2];
#pragma unroll
                for (int mi = 0; mi < 2; mi++)
                    wmma::load_matrix_sync(af[mi], sP + (wm * 32 + mi * 16) * PLDH + k, PLDH);
                wmma::fragment<wmma::matrix_b, 16, 16, 16, __half, wmma::row_major> bf[2];
#pragma unroll
                for (int ni = 0; ni < 2; ni++)
                    wmma::load_matrix_sync(bf[ni], sV + k * QLDH + wn * 32 + ni * 16, QLDH);
#pragma unroll
                for (int mi = 0; mi < 2; mi++)
#pragma unroll
                    for (int ni = 0; ni < 2; ni++)
                        wmma::mma_sync(oacc[mi][ni], af[mi], bf[ni], oacc[mi][ni]);
            }
        }
        __syncthreads();
        if (t + 1 < nt) { loadT(base + 512 + (long)(t + 1) * 128 * 768, sV); CPA_COMMIT(); }
    }

    if (tid < 128) al[tid] = 1.f / lrow[tid];
    __syncthreads();
    {
        float iv[2][8];
#pragma unroll
        for (int mi = 0; mi < 2; mi++)
#pragma unroll
            for (int e = 0; e < 8; e++)
                iv[mi][e] = al[wm * 32 + mi * 16 + rt[e]];
#pragma unroll
        for (int mi = 0; mi < 2; mi++)
#pragma unroll
            for (int ni = 0; ni < 2; ni++) {
#pragma unroll
                for (int e = 0; e < 8; e++) oacc[mi][ni].x[e] *= iv[mi][e];
                wmma::store_matrix_sync(sS + (wm * 32 + mi * 16) * SLDF + wn * 32 + ni * 16,
                                        oacc[mi][ni], SLDF, wmma::mem_row_major);
            }
    }
    __syncthreads();
    {
        __half* outp = ctx + ((long)b * SEQ + segOff + (long)qt * 128) * HID + h * 64;
#pragma unroll 4
        for (int i = 0; i < 16; i++) {
            int idx = tid + i * 256;
            int r = idx >> 5, c = (idx & 31) * 2;
            float v0 = sS[r * SLDF + c];
            float v1 = sS[r * SLDF + c + 1];
            *(__half2*)(outp + (long)r * HID + c) = __floats2half2_rn(v0, v1);
        }
    }
}

// -------------------- final --------------------------------------------------
__global__ void final_k(const float* __restrict__ mean, const float* __restrict__ W,
                        const float* __restrict__ bias, float* __restrict__ out)
{
    int b = blockIdx.x, n = threadIdx.x;
    __shared__ float comb[HID];
    const float* mp = mean + (long)b * 3 * HID;
    comb[n] = mp[n] * (1.f / 512.f) - mp[HID + n] * (1.f / 256.f)
            + mp[2 * HID + n] * (1.f / 256.f);
    __syncthreads();
    float s = bias[n];
#pragma unroll 8
    for (int k = 0; k < HID; k++) s += comb[k] * W[k * HID + n];
    out[(long)b * HID + n] = fmaxf(s, 0.f);
}

// ---------------------------------------------------------------------------
static void launch_gemm(const __half* A, const __half* B, const float* bias,
                        __half* C16, float* C32,
                        int M, int N, int K, int lda, int ldb, int ldc,
                        long sAb, long sBb, long sCb, int batches, int relu)
{
    dim3 grid(N / 256, M / 128, batches);
    gemm_w_h<<<grid, 256, GEMM_SMEM_BYTES>>>(A, B, bias, C16, C32, K, lda, ldb, ldc,
                                             sAb, sBb, sCb, relu);
}

extern "C" void kernel_launch(void* const* d_in, const int* in_sizes, int n_in,
                              void* d_out, int out_size)
{
    const int*   hyper = (const int*)  d_in[0];
    const float* HT    = (const float*)d_in[1];
    const float* emb   = (const float*)d_in[2];
    const float* Wg1   = (const float*)d_in[3];
    const float* bg1   = (const float*)d_in[4];
    const float* Wg2   = (const float*)d_in[5];
    const float* bg2   = (const float*)d_in[6];
    const float* Wqkv  = (const float*)d_in[7];
    const float* bqkv  = (const float*)d_in[8];
    const float* Wo    = (const float*)d_in[9];
    const float* bo    = (const float*)d_in[10];
    const float* ln1g  = (const float*)d_in[11];
    const float* ln1b  = (const float*)d_in[12];
    const float* Wff1  = (const float*)d_in[13];
    const float* bff1  = (const float*)d_in[14];
    const float* Wff2  = (const float*)d_in[15];
    const float* bff2  = (const float*)d_in[16];
    const float* ln2g  = (const float*)d_in[17];
    const float* ln2b  = (const float*)d_in[18];
    const float* fc1W  = (const float*)d_in[19];
    const float* fc1b  = (const float*)d_in[20];

    __half *hth, *h0h, *th, *xh, *x1h, *qkvh, *ctxh, *ffh;
    __half *wg1h, *wg2h, *wqkvh, *woh, *w1ph, *w2ph;
    float *x32, *x132, *mean, *b1p;
    int *rowtab;
    cudaGetSymbolAddress((void**)&hth,   g_hth);
    cudaGetSymbolAddress((void**)&h0h,   g_h0h);
    cudaGetSymbolAddress((void**)&th,    g_th);
    cudaGetSymbolAddress((void**)&xh,    g_xh);
    cudaGetSymbolAddress((void**)&x32,   g_x32);
    cudaGetSymbolAddress((void**)&x1h,   g_x1h);
    cudaGetSymbolAddress((void**)&x132,  g_x132);
    cudaGetSymbolAddress((void**)&qkvh,  g_qkvh);
    cudaGetSymbolAddress((void**)&ctxh,  g_ctxh);
    cudaGetSymbolAddress((void**)&ffh,   g_ffh);
    cudaGetSymbolAddress((void**)&mean,  g_mean);
    cudaGetSymbolAddress((void**)&wg1h,  g_wg1h);
    cudaGetSymbolAddress((void**)&wg2h,  g_wg2h);
    cudaGetSymbolAddress((void**)&wqkvh, g_wqkvh);
    cudaGetSymbolAddress((void**)&woh,   g_woh);
    cudaGetSymbolAddress((void**)&w1ph,  g_w1ph);
    cudaGetSymbolAddress((void**)&b1p,   g_b1p);
    cudaGetSymbolAddress((void**)&w2ph,  g_w2ph);
    cudaGetSymbolAddress((void**)&rowtab, g_rowtab);

    cudaFuncSetAttribute(flash_k, cudaFuncAttributeMaxDynamicSharedMemorySize,
                         FLASH_SMEM_BYTES);
    cudaFuncSetAttribute(gemm_w_h, cudaFuncAttributeMaxDynamicSharedMemorySize,
                         GEMM_SMEM_BYTES);
    cudaFuncSetAttribute(gemm_ln_h, cudaFuncAttributeMaxDynamicSharedMemorySize,
                         LN_SMEM_BYTES);

    // 0. probe + conversions
    probe_k<<<1, 32>>>(rowtab);
    cvt4_k<<<(NB * SEQ * SEQ / 4 + 255) / 256, 256>>>((const float4*)HT,
                                                      (__half2*)hth, NB * SEQ * SEQ / 4);
    gather_h_k<<<TOKENS, 64>>>(hyper, emb, h0h);
    prep_w_k<<<(668160 + 255) / 256, 256>>>(Wg1, Wg2, Wqkv, Wo, Wff1, bff1, Wff2,
                                            wg1h, wg2h, wqkvh, woh, w1ph, b1p, w2ph,
                                            mean);

    // 1. t = h0 @ Wg1
    launch_gemm(h0h, wg1h, nullptr, th, nullptr, TOKENS, HID, HID, HID, HID, HID,
                0, 0, 0, 1, 0);

    // 2. x = batched HT @ t + bg1
    launch_gemm(hth, th, bg1, xh, nullptr, SEQ, HID, SEQ, SEQ, HID, HID,
                (long)SEQ * SEQ, (long)SEQ * HID, (long)SEQ * HID, NB, 0);

    // 3. t = x @ Wg2
    launch_gemm(xh, wg2h, nullptr, th, nullptr, TOKENS, HID, HID, HID, HID, HID,
                0, 0, 0, 1, 0);

    // 4. x = batched HT @ t + bg2   (fp16 + fp32 residual)
    launch_gemm(hth, th, bg2, xh, x32, SEQ, HID, SEQ, SEQ, HID, HID,
                (long)SEQ * SEQ, (long)SEQ * HID, (long)SEQ * HID, NB, 0);

    // 5. qkv = x @ Wqkv + bqkv
    launch_gemm(xh, wqkvh, bqkv, qkvh, nullptr, TOKENS, 3 * HID, HID,
                HID, 3 * HID, 3 * HID, 0, 0, 0, 1, 0);

    // 6. flash attention (single launch)
    flash_k<<<dim3(8, NB * NHEADS), 256, FLASH_SMEM_BYTES>>>(qkvh, ctxh, rowtab);

    // 7. x1 = LN1(x + ctx @ Wo + bo)
    gemm_ln_h<<<TOKENS / 128, 256, LN_SMEM_BYTES>>>(ctxh, woh, bo, x32,
                                                    ln1g, ln1b, x132, x1h, nullptr,
                                                    HID, HID);

    // 8. ff = relu(x1 @ w1p + b1p)
    launch_gemm(x1h, w1ph, b1p, ffh, nullptr, TOKENS, FFP, HID, HID, FFP, FFP,
                0, 0, 0, 1, 1);

    // 9. LN2 + segment mean fused (no gmem LN2 output)
    gemm_ln_h<<<TOKENS / 128, 256, LN_SMEM_BYTES>>>(ffh, w2ph, bff2, x132,
                                                    ln2g, ln2b, nullptr, nullptr,
                                                    mean, FFP, FFP);

    // 10. out = relu((p - n + f) @ fc1W + fc1b)
    final_k<<<NB, 256>>>(mean, fc1W, fc1b, (float*)d_out);
}

// round 16
// speedup vs baseline: 1.0882x; 1.0882x over previous
#include <cuda_runtime.h>
#include <cuda_fp16.h>
#include <mma.h>

using namespace nvcuda;

// ---------------------------------------------------------------------------
// GraphEncoder: fp16 TC GEMMs (128x128 CTA, 4-stage), fp16 residuals,
// LN2+mean fused. B=16, S=1024 (512/256/256), H=256, heads=4, F=400.
// ---------------------------------------------------------------------------

#define NB 16
#define SEQ 1024
#define HID 256
#define NHEADS 4
#define DH 64
#define FFP 512
#define TOKENS (NB * SEQ)

// -------------------- scratch (device globals; no allocation) --------------
__device__ __half g_hth[NB * SEQ * SEQ];
__device__ __half g_h0h[TOKENS * HID];
__device__ __half g_th[TOKENS * HID];
__device__ __half g_xh[TOKENS * HID];
__device__ __half g_x1h[TOKENS * HID];
__device__ __half g_qkvh[TOKENS * 3 * HID];
__device__ __half g_ctxh[TOKENS * HID];
__device__ __half g_ffh[TOKENS * FFP];
__device__ float  g_mean[NB * 3 * HID];
__device__ __half g_wg1h[HID * HID];
__device__ __half g_wg2h[HID * HID];
__device__ __half g_wqkvh[HID * 3 * HID];
__device__ __half g_woh[HID * HID];
__device__ __half g_w1ph[HID * FFP];
__device__ float  g_b1p[FFP];
__device__ __half g_w2ph[FFP * HID];
__device__ int    g_rowtab[256];

__device__ __forceinline__ unsigned sptr(const void* p) {
    return (unsigned)__cvta_generic_to_shared(p);
}
#define CPA16(dst, src) asm volatile("cp.async.ca.shared.global [%0], [%1], 16;" :: "r"(dst), "l"(src))
#define CPA_COMMIT()    asm volatile("cp.async.commit_group;")
#define CPA_WAIT0()     asm volatile("cp.async.wait_group 0;")
#define CPA_WAIT1()     asm volatile("cp.async.wait_group 1;")
#define CPA_WAIT2()     asm volatile("cp.async.wait_group 2;")

// FMA-pipe exp2 (no MUFU)
__device__ __forceinline__ float fexp2(float y) {
    y = fmaxf(y, -80.f);
    float t = y + 12582912.f;
    int   n = __float_as_int(t) - 0x4B400000;
    float f = y - (t - 12582912.f);
    float p = 1.f + f * (0.69314718f + f * (0.24022651f +
                   f * (0.05550411f + f * 0.00961813f)));
    return __int_as_float(__float_as_int(p) + (n << 23));
}
#define SM_SCALE 0.18033688f   // 0.125 * log2(e)

// -------------------- probe: fp32 acc element->row map ---------------------
__global__ void probe_k(int* __restrict__ rowtab)
{
    __shared__ float pat[16 * 16];
    int lane = threadIdx.x;
    wmma::fragment<wmma::accumulator, 16, 16, 16, float> fr;
    for (int i = lane; i < 256; i += 32) pat[i] = (float)(i >> 4);
    __syncwarp();
    wmma::load_matrix_sync(fr, pat, 16, wmma::mem_row_major);
#pragma unroll
    for (int e = 0; e < 8; e++) rowtab[lane * 8 + e] = (int)fr.x[e];
}

// -------------------- prep kernels -----------------------------------------
__global__ void cvt4_k(const float4* __restrict__ in, __half2* __restrict__ out, int n4)
{
    int i = blockIdx.x * 256 + threadIdx.x;
    if (i < n4) {
        float4 v = in[i];
        out[i * 2]     = __floats2half2_rn(v.x, v.y);
        out[i * 2 + 1] = __floats2half2_rn(v.z, v.w);
    }
}
__global__ void gather_h_k(const int* __restrict__ idx, const float* __restrict__ tab,
                           __half* __restrict__ out)
{
    long tok = blockIdx.x;
    int id = idx[tok];
    const float4 v = ((const float4*)(tab + (long)id * HID))[threadIdx.x];
    __half2* dst = (__half2*)(out + tok * HID) + threadIdx.x * 2;
    dst[0] = __floats2half2_rn(v.x, v.y);
    dst[1] = __floats2half2_rn(v.z, v.w);
}
__global__ void prep_w_k(
    const float* __restrict__ Wg1, const float* __restrict__ Wg2,
    const float* __restrict__ Wqkv, const float* __restrict__ Wo,
    const float* __restrict__ Wff1, const float* __restrict__ bff1,
    const float* __restrict__ Wff2,
    __half* __restrict__ wg1h, __half* __restrict__ wg2h,
    __half* __restrict__ wqkvh, __half* __restrict__ woh,
    __half* __restrict__ w1ph, float* __restrict__ b1p,
    __half* __restrict__ w2ph, float* __restrict__ mean)
{
    int i = blockIdx.x * 256 + threadIdx.x;
    if (i < 65536) { wg1h[i] = __float2half(Wg1[i]); return; }
    i -= 65536;
    if (i < 65536) { wg2h[i] = __float2half(Wg2[i]); return; }
    i -= 65536;
    if (i < 196608) { wqkvh[i] = __float2half(Wqkv[i]); return; }
    i -= 196608;
    if (i < 65536) { woh[i] = __float2half(Wo[i]); return; }
    i -= 65536;
    if (i < 131072) {
        int r = i >> 9, c = i & 511;
        w1ph[i] = __float2half((c < 400) ? Wff1[r * 400 + c] : 0.f);
        return;
    }
    i -= 131072;
    if (i < 131072) {
        int r = i >> 8, c = i & 255;
        w2ph[i] = __float2half((r < 400) ? Wff2[r * 256 + c] : 0.f);
        return;
    }
    i -= 131072;
    if (i < 512) { b1p[i] = (i < 400) ? bff1[i] : 0.f; return; }
    i -= 512;
    if (i < NB * 3 * HID) mean[i] = 0.f;
}

// -------------------- fp16 GEMM (128x128 CTA, 128 thr, 4-stage) ------------
#define BKH 32
#define APH 40
#define BPH 136
#define ASH (128 * APH)
#define BSH (BKH * BPH)
#define STAGES 4
#define EPLD 132
#define PIPE_BYTES (STAGES * (ASH + BSH) * 2)
#define GEMM_SMEM_BYTES (PIPE_BYTES > 128 * EPLD * 4 ? PIPE_BYTES : 128 * EPLD * 4)

__global__ void __launch_bounds__(128, 2) gemm_h(
    const __half* __restrict__ A, const __half* __restrict__ Bm,
    const float* __restrict__ bias, __half* __restrict__ C16,
    int K, int lda, int ldb, int ldc,
    long sAb, long sBb, long sCb, int relu)
{
    extern __shared__ __half smh[];

    const int z = blockIdx.z;
    A  += (long)z * sAb;
    Bm += (long)z * sBb;

    const int tid = threadIdx.x;
    const int w = tid >> 5;
    const int wm = w & 1, wn = w >> 1;
    const int rowTile = blockIdx.y * 128;
    const int colTile = blockIdx.x * 128;

    auto loadA = [&](int kt, int s) {
        const __half* Ag = A + (long)rowTile * lda + kt * BKH;
        __half* sa = smh + s * ASH;
#pragma unroll
        for (int i = 0; i < 4; i++) {
            int idx = tid + i * 128;
            int r = idx >> 2, c8 = (idx & 3) * 8;
            CPA16(sptr(sa + r * APH + c8), Ag + (long)r * lda + c8);
        }
    };
    auto loadB = [&](int kt, int s) {
        const __half* Bg = Bm + (long)(kt * BKH) * ldb + colTile;
        __half* sb = smh + STAGES * ASH + s * BSH;
#pragma unroll
        for (int i = 0; i < 4; i++) {
            int idx = tid + i * 128;
            int r = idx >> 4, c8 = (idx & 15) * 8;
            CPA16(sptr(sb + r * BPH + c8), Bg + (long)r * ldb + c8);
        }
    };

    loadA(0, 0); loadB(0, 0); CPA_COMMIT();
    loadA(1, 1); loadB(1, 1); CPA_COMMIT();
    loadA(2, 2); loadB(2, 2); CPA_COMMIT();

    wmma::fragment<wmma::accumulator, 16, 16, 16, float> acc[4][4];
#pragma unroll
    for (int mi = 0; mi < 4; mi++)
#pragma unroll
        for (int ni = 0; ni < 4; ni++) wmma::fill_fragment(acc[mi][ni], 0.f);

    const int nk = K / BKH;
    for (int kt = 0; kt < nk; kt++) {
        CPA_WAIT2();
        __syncthreads();
        if (kt + 3 < nk) { int s = (kt + 3) % STAGES; loadA(kt + 3, s); loadB(kt + 3, s); CPA_COMMIT(); }

        const __half* sa = smh + (kt % STAGES) * ASH;
        const __half* sb = smh + STAGES * ASH + (kt % STAGES) * BSH;

#pragma unroll
        for (int ks = 0; ks < 2; ks++) {
            wmma::fragment<wmma::matrix_a, 16, 16, 16, __half, wmma::row_major> af[4];
#pragma unroll
            for (int mi = 0; mi < 4; mi++)
                wmma::load_matrix_sync(af[mi], sa + (wm * 64 + mi * 16) * APH + ks * 16, APH);
            wmma::fragment<wmma::matrix_b, 16, 16, 16, __half, wmma::row_major> bf[4];
#pragma unroll
            for (int ni = 0; ni < 4; ni++)
                wmma::load_matrix_sync(bf[ni], sb + (ks * 16) * BPH + wn * 64 + ni * 16, BPH);
#pragma unroll
            for (int mi = 0; mi < 4; mi++)
#pragma unroll
                for (int ni = 0; ni < 4; ni++)
                    wmma::mma_sync(acc[mi][ni], af[mi], bf[ni], acc[mi][ni]);
        }
    }
    CPA_WAIT0();
    __syncthreads();

    float* epi = (float*)smh;
#pragma unroll
    for (int mi = 0; mi < 4; mi++)
#pragma unroll
        for (int ni = 0; ni < 4; ni++)
            wmma::store_matrix_sync(epi + (wm * 64 + mi * 16) * EPLD + wn * 64 + ni * 16,
                                    acc[mi][ni], EPLD, wmma::mem_row_major);
    __syncthreads();

    __half* C16z = C16 + (long)z * sCb;
#pragma unroll 4
    for (int i = 0; i < 64; i++) {
        int idx = tid + i * 128;
        int r = idx >> 6, c = (idx & 63) * 2;
        float v0 = epi[r * EPLD + c];
        float v1 = epi[r * EPLD + c + 1];
        if (bias) { v0 += bias[colTile + c]; v1 += bias[colTile + c + 1]; }
        if (relu) { v0 = fmaxf(v0, 0.f); v1 = fmaxf(v1, 0.f); }
        long off = (long)(rowTile + r) * ldc + colTile + c;
        *(__half2*)(C16z + off) = __floats2half2_rn(v0, v1);
    }
}

// -------------------- fp16 GEMM + residual(LN) (+ fused mean) --------------
// residual read as fp16. out16 written unless meanout path.
#define LSTAGES 3
#define LAPH 40
#define LBPH 264
#define LASH (128 * LAPH)
#define LBSH (BKH * LBPH)
#define LEPI_OFF (LSTAGES * (LASH + LBSH))
#define LBPADF 260
#define LN_SMEM_BYTES (LEPI_OFF * 2 + (128 * LBPADF + 2 * 128) * 4)

__global__ void __launch_bounds__(256, 1) gemm_ln_h(
    const __half* __restrict__ A, const __half* __restrict__ Bm,
    const float* __restrict__ bias, const __half* __restrict__ res,
    const float* __restrict__ lng, const float* __restrict__ lnb,
    __half* __restrict__ out16, float* __restrict__ meanout, int K, int lda)
{
    extern __shared__ __half smh[];
    float* epi = (float*)(smh + LEPI_OFF);
    float* smu = epi + 128 * LBPADF;
    float* srs = smu + 128;

    const int tid = threadIdx.x;
    const int w = tid >> 5;
    const int wm = w & 1, wn = w >> 1;
    const int rowTile = blockIdx.x * 128;

    auto loadA = [&](int kt, int s) {
        const __half* Ag = A + (long)rowTile * lda + kt * BKH;
        __half* sa = smh + s * LASH;
#pragma unroll
        for (int i = 0; i < 2; i++) {
            int idx = tid + i * 256;
            int r = idx >> 2, c8 = (idx & 3) * 8;
            CPA16(sptr(sa + r * LAPH + c8), Ag + (long)r * lda + c8);
        }
    };
    auto loadB = [&](int kt, int s) {
        const __half* Bg = Bm + (long)(kt * BKH) * 256;
        __half* sb = smh + LSTAGES * LASH + s * LBSH;
#pragma unroll
        for (int i = 0; i < 4; i++) {
            int idx = tid + i * 256;
            int r = idx >> 5, c8 = (idx & 31) * 8;
            CPA16(sptr(sb + r * LBPH + c8), Bg + (long)r * 256 + c8);
        }
    };

    loadA(0, 0); loadB(0, 0); CPA_COMMIT();
    loadA(1, 1); loadB(1, 1); CPA_COMMIT();

    wmma::fragment<wmma::accumulator, 16, 16, 16, float> acc[4][4];
#pragma unroll
    for (int mi = 0; mi < 4; mi++)
#pragma unroll
        for (int ni = 0; ni < 4; ni++) wmma::fill_fragment(acc[mi][ni], 0.f);

    const int nk = K / BKH;
    for (int kt = 0; kt < nk; kt++) {
        CPA_WAIT1();
        __syncthreads();
        if (kt + 2 < nk) { int s = (kt + 2) % LSTAGES; loadA(kt + 2, s); loadB(kt + 2, s); CPA_COMMIT(); }

        const __half* sa = smh + (kt % LSTAGES) * LASH;
        const __half* sb = smh + LSTAGES * LASH + (kt % LSTAGES) * LBSH;

#pragma unroll
        for (int ks = 0; ks < 2; ks++) {
            wmma::fragment<wmma::matrix_a, 16, 16, 16, __half, wmma::row_major> af[4];
#pragma unroll
            for (int mi = 0; mi < 4; mi++)
                wmma::load_matrix_sync(af[mi], sa + (wm * 64 + mi * 16) * LAPH + ks * 16, LAPH);
            wmma::fragment<wmma::matrix_b, 16, 16, 16, __half, wmma::row_major> bf[4];
#pragma unroll
            for (int ni = 0; ni < 4; ni++)
                wmma::load_matrix_sync(bf[ni], sb + (ks * 16) * LBPH + wn * 64 + ni * 16, LBPH);
#pragma unroll
            for (int mi = 0; mi < 4; mi++)
#pragma unroll
                for (int ni = 0; ni < 4; ni++)
                    wmma::mma_sync(acc[mi][ni], af[mi], bf[ni], acc[mi][ni]);
        }
    }
    __syncthreads();

#pragma unroll
    for (int mi = 0; mi < 4; mi++)
#pragma unroll
        for (int ni = 0; ni < 4; ni++)
            wmma::store_matrix_sync(epi + (wm * 64 + mi * 16) * LBPADF + wn * 64 + ni * 16,
                                    acc[mi][ni], LBPADF, wmma::mem_row_major);
    __syncthreads();

    // add bias + fp16 residual (vectorized half2 read)
#pragma unroll 4
    for (int i = 0; i < 64; i++) {
        int idx = tid + i * 256;                // 16384 pairs
        int r = idx >> 7, c = (idx & 127) * 2;
        __half2 rv = *(const __half2*)(res + (long)(rowTile + r) * HID + c);
        float2 rf = __half22float2(rv);
        epi[r * LBPADF + c]     += bias[c]     + rf.x;
        epi[r * LBPADF + c + 1] += bias[c + 1] + rf.y;
    }
    __syncthreads();

    {
        const int r = tid >> 1, hf = tid & 1;
        const float* row = epi + r * LBPADF + hf * 128;
        float s = 0.f, s2 = 0.f;
#pragma unroll 8
        for (int c = 0; c < 128; c++) { float v = row[c]; s += v; s2 += v * v; }
        s  += __shfl_xor_sync(0xffffffffu, s, 1);
        s2 += __shfl_xor_sync(0xffffffffu, s2, 1);
        if (hf == 0) {
            float mu = s * (1.f / 256.f);
            float var = s2 * (1.f / 256.f) - mu * mu;
            smu[r] = mu;
            srs[r] = rsqrtf(var + 1e-5f);
        }
    }
    __syncthreads();

    if (meanout) {
        int grow = rowTile;
        int b = grow >> 10, pos = grow & 1023;
        int sgi = (pos < 512) ? 0 : ((pos < 768) ? 1 : 2);
        int seg = b * 3 + sgi;
        const int c = tid;
        float s = 0.f;
#pragma unroll 8
        for (int r = 0; r < 128; r++)
            s += (epi[r * LBPADF + c] - smu[r]) * srs[r];
        atomicAdd(&meanout[(long)seg * HID + c], s * lng[c] + 128.f * lnb[c]);
    } else {
#pragma unroll 4
        for (int i = 0; i < 64; i++) {
            int idx = tid + i * 256;
            int r = idx >> 7, c = (idx & 127) * 2;
            float v0 = (epi[r * LBPADF + c]     - smu[r]) * srs[r] * lng[c]     + lnb[c];
            float v1 = (epi[r * LBPADF + c + 1] - smu[r]) * srs[r] * lng[c + 1] + lnb[c + 1];
            *(__half2*)(out16 + (long)(rowTile + r) * HID + c) = __floats2half2_rn(v0, v1);
        }
    }
}

// -------------------- fp16 flash attention ---------------------------------
#define QLDH 72
#define SLDF 132
#define PLDH 136
#define FS_Q 0
#define FS_K (128 * QLDH)
#define FS_V (2 * 128 * QLDH)
#define FS_P (3 * 128 * QLDH)
#define FS_F 45056
#define FLASH_SMEM_BYTES (FS_F * 2 + (128 * SLDF + 3 * 128) * 4)

__global__ void __launch_bounds__(256) flash_k(
    const __half* __restrict__ qkv, __half* __restrict__ ctx,
    const int* __restrict__ rowtab)
{
    extern __shared__ __half smh[];
    __half* sQ = smh + FS_Q;
    __half* sK = smh + FS_K;
    __half* sV = smh + FS_V;
    __half* sP = smh + FS_P;
    float* sS = (float*)(smh + FS_F);
    float* al = sS + 128 * SLDF;
    float* mrow = al + 128;
    float* lrow = mrow + 128;

    const int bx = blockIdx.x;
    int segOff, L, qt;
    if (bx < 4)      { segOff = 0;   L = 512; qt = bx; }
    else if (bx < 6) { segOff = 512; L = 256; qt = bx - 4; }
    else             { segOff = 768; L = 256; qt = bx - 6; }

    const int bh = blockIdx.y;
    const int b = bh >> 2, h = bh & 3;
    const int tid = threadIdx.x;
    const int w = tid >> 5, lane = tid & 31;
    const int wm = w & 3, wn = w >> 2;

    const __half* base = qkv + ((long)b * SEQ + segOff) * 768 + h * 64;

    auto loadT = [&](const __half* g, __half* s) {
#pragma unroll
        for (int i = 0; i < 4; i++) {
            int idx = tid + i * 256;
            int r = idx >> 3, c8 = (idx & 7) * 8;
            CPA16(sptr(s + r * QLDH + c8), g + (long)r * 768 + c8);
        }
    };

    int rt[8];
#pragma unroll
    for (int e = 0; e < 8; e++) rt[e] = rowtab[lane * 8 + e];

    if (tid < 128) { mrow[tid] = -1e30f; lrow[tid] = 0.f; }

    loadT(base + (long)qt * 128 * 768, sQ);
    loadT(base + 256, sK); CPA_COMMIT();
    loadT(base + 512, sV); CPA_COMMIT();

    wmma::fragment<wmma::accumulator, 16, 16, 16, float> oacc[2][2];
#pragma unroll
    for (int mi = 0; mi < 2; mi++)
#pragma unroll
        for (int ni = 0; ni < 2; ni++) wmma::fill_fragment(oacc[mi][ni], 0.f);

    const int nt = L >> 7;
    for (int t = 0; t < nt; t++) {
        CPA_WAIT1();
        __syncthreads();

        {
            wmma::fragment<wmma::accumulator, 16, 16, 16, float> sacc[2][4];
#pragma unroll
            for (int mi = 0; mi < 2; mi++)
#pragma unroll
                for (int ni = 0; ni < 4; ni++) wmma::fill_fragment(sacc[mi][ni], 0.f);
#pragma unroll
            for (int k = 0; k < DH; k += 16) {
                wmma::fragment<wmma::matrix_a, 16, 16, 16, __half, wmma::row_major> af[2];
#pragma unroll
                for (int mi = 0; mi < 2; mi++)
                    wmma::load_matrix_sync(af[mi], sQ + (wm * 32 + mi * 16) * QLDH + k, QLDH);
                wmma::fragment<wmma::matrix_b, 16, 16, 16, __half, wmma::col_major> bf[4];
#pragma unroll
                for (int ni = 0; ni < 4; ni++)
                    wmma::load_matrix_sync(bf[ni], sK + (wn * 64 + ni * 16) * QLDH + k, QLDH);
#pragma unroll
                for (int mi = 0; mi < 2; mi++)
#pragma unroll
                    for (int ni = 0; ni < 4; ni++)
                        wmma::mma_sync(sacc[mi][ni], af[mi], bf[ni], sacc[mi][ni]);
            }
#pragma unroll
            for (int mi = 0; mi < 2; mi++)
#pragma unroll
                for (int ni = 0; ni < 4; ni++)
                    wmma::store_matrix_sync(sS + (wm * 32 + mi * 16) * SLDF + wn * 64 + ni * 16,
                                            sacc[mi][ni], SLDF, wmma::mem_row_major);
        }
        __syncthreads();

        if (t + 1 < nt) { loadT(base + 256 + (long)(t + 1) * 128 * 768, sK); CPA_COMMIT(); }

        {
            const int r = tid >> 1, hf = tid & 1;
            float* row = sS + r * SLDF + hf * 64;
            __half* prow = sP + r * PLDH + hf * 64;
            float mx = -1e30f;
#pragma unroll 8
            for (int c = 0; c < 64; c++) mx = fmaxf(mx, row[c]);
            mx = fmaxf(mx, __shfl_xor_sync(0xffffffffu, mx, 1));
            mx *= SM_SCALE;
            float m_old = mrow[r];
            float m_new = fmaxf(m_old, mx);
            float a = fexp2(m_old - m_new);
            float sum = 0.f;
#pragma unroll 4
            for (int c = 0; c < 64; c++) {
                float p = fexp2(row[c] * SM_SCALE - m_new);
                prow[c] = __float2half(p);
                sum += p;
            }
            sum += __shfl_xor_sync(0xffffffffu, sum, 1);
            if (hf == 0) {
                mrow[r] = m_new;
                lrow[r] = lrow[r] * a + sum;
                al[r] = a;
            }
        }
        if (t + 1 < nt) { CPA_WAIT1(); } else { CPA_WAIT0(); }
        __syncthreads();

        {
            float av[2][8];
#pragma unroll
            for (int mi = 0; mi < 2; mi++)
#pragma unroll
                for (int e = 0; e < 8; e++)
                    av[mi][e] = al[wm * 32 + mi * 16 + rt[e]];
#pragma unroll
            for (int mi = 0; mi < 2; mi++)
#pragma unroll
                for (int ni = 0; ni < 2; ni++)
#pragma unroll
                    for (int e = 0; e < 8; e++)
                        oacc[mi][ni].x[e] *= av[mi][e];

#pragma unroll
            for (int k = 0; k < 128; k += 16) {
                wmma::fragment<wmma::matrix_a, 16, 16, 16, __half, wmma::row_major> af[2];
#pragma unroll
                for (int mi = 0; mi < 2; mi++)
                    wmma::load_matrix_sync(af[mi], sP + (wm * 32 + mi * 16) * PLDH + k, PLDH);
                wmma::fragment<wmma::matrix_b, 16, 16, 16, __half, wmma::row_major> bf[2];
#pragma unroll
                for (int ni = 0; ni < 2; ni++)
                    wmma::load_matrix_sync(bf[ni], sV + k * QLDH + wn * 32 + ni * 16, QLDH);
#pragma unroll
                for (int mi = 0; mi < 2; mi++)
#pragma unroll
                    for (int ni = 0; ni < 2; ni++)
                        wmma::mma_sync(oacc[mi][ni], af[mi], bf[ni], oacc[mi][ni]);
            }
        }
        __syncthreads();
        if (t + 1 < nt) { loadT(base + 512 + (long)(t + 1) * 128 * 768, sV); CPA_COMMIT(); }
    }

    if (tid < 128) al[tid] = 1.f / lrow[tid];
    __syncthreads();
    {
        float iv[2][8];
#pragma unroll
        for (int mi = 0; mi < 2; mi++)
#pragma unroll
            for (int e = 0; e < 8; e++)
                iv[mi][e] = al[wm * 32 + mi * 16 + rt[e]];
#pragma unroll
        for (int mi = 0; mi < 2; mi++)
#pragma unroll
            for (int ni = 0; ni < 2; ni++) {
#pragma unroll
                for (int e = 0; e < 8; e++) oacc[mi][ni].x[e] *= iv[mi][e];
                wmma::store_matrix_sync(sS + (wm * 32 + mi * 16) * SLDF + wn * 32 + ni * 16,
                                        oacc[mi][ni], SLDF, wmma::mem_row_major);
            }
    }
    __syncthreads();
    {
        __half* outp = ctx + ((long)b * SEQ + segOff + (long)qt * 128) * HID + h * 64;
#pragma unroll 4
        for (int i = 0; i < 16; i++) {
            int idx = tid + i * 256;
            int r = idx >> 5, c = (idx & 31) * 2;
            float v0 = sS[r * SLDF + c];
            float v1 = sS[r * SLDF + c + 1];
            *(__half2*)(outp + (long)r * HID + c) = __floats2half2_rn(v0, v1);
        }
    }
}

// -------------------- final --------------------------------------------------
__global__ void final_k(const float* __restrict__ mean, const float* __restrict__ W,
                        const float* __restrict__ bias, float* __restrict__ out)
{
    int b = blockIdx.x, n = threadIdx.x;
    __shared__ float comb[HID];
    const float* mp = mean + (long)b * 3 * HID;
    comb[n] = mp[n] * (1.f / 512.f) - mp[HID + n] * (1.f / 256.f)
            + mp[2 * HID + n] * (1.f / 256.f);
    __syncthreads();
    float s = bias[n];
#pragma unroll 8
    for (int k = 0; k < HID; k++) s += comb[k] * W[k * HID + n];
    out[(long)b * HID + n] = fmaxf(s, 0.f);
}

// ---------------------------------------------------------------------------
static void launch_gemm(const __half* A, const __half* B, const float* bias,
                        __half* C16,
                        int M, int N, int K, int lda, int ldb, int ldc,
                        long sAb, long sBb, long sCb, int batches, int relu)
{
    dim3 grid(N / 128, M / 128, batches);
    gemm_h<<<grid, 128, GEMM_SMEM_BYTES>>>(A, B, bias, C16, K, lda, ldb, ldc,
                                           sAb, sBb, sCb, relu);
}

extern "C" void kernel_launch(void* const* d_in, const int* in_sizes, int n_in,
                              void* d_out, int out_size)
{
    const int*   hyper = (const int*)  d_in[0];
    const float* HT    = (const float*)d_in[1];
    const float* emb   = (const float*)d_in[2];
    const float* Wg1   = (const float*)d_in[3];
    const float* bg1   = (const float*)d_in[4];
    const float* Wg2   = (const float*)d_in[5];
    const float* bg2   = (const float*)d_in[6];
    const float* Wqkv  = (const float*)d_in[7];
    const float* bqkv  = (const float*)d_in[8];
    const float* Wo    = (const float*)d_in[9];
    const float* bo    = (const float*)d_in[10];
    const float* ln1g  = (const float*)d_in[11];
    const float* ln1b  = (const float*)d_in[12];
    const float* Wff1  = (const float*)d_in[13];
    const float* bff1  = (const float*)d_in[14];
    const float* Wff2  = (const float*)d_in[15];
    const float* bff2  = (const float*)d_in[16];
    const float* ln2g  = (const float*)d_in[17];
    const float* ln2b  = (const float*)d_in[18];
    const float* fc1W  = (const float*)d_in[19];
    const float* fc1b  = (const float*)d_in[20];

    __half *hth, *h0h, *th, *xh, *x1h, *qkvh, *ctxh, *ffh;
    __half *wg1h, *wg2h, *wqkvh, *woh, *w1ph, *w2ph;
    float *mean, *b1p;
    int *rowtab;
    cudaGetSymbolAddress((void**)&hth,   g_hth);
    cudaGetSymbolAddress((void**)&h0h,   g_h0h);
    cudaGetSymbolAddress((void**)&th,    g_th);
    cudaGetSymbolAddress((void**)&xh,    g_xh);
    cudaGetSymbolAddress((void**)&x1h,   g_x1h);
    cudaGetSymbolAddress((void**)&qkvh,  g_qkvh);
    cudaGetSymbolAddress((void**)&ctxh,  g_ctxh);
    cudaGetSymbolAddress((void**)&ffh,   g_ffh);
    cudaGetSymbolAddress((void**)&mean,  g_mean);
    cudaGetSymbolAddress((void**)&wg1h,  g_wg1h);
    cudaGetSymbolAddress((void**)&wg2h,  g_wg2h);
    cudaGetSymbolAddress((void**)&wqkvh, g_wqkvh);
    cudaGetSymbolAddress((void**)&woh,   g_woh);
    cudaGetSymbolAddress((void**)&w1ph,  g_w1ph);
    cudaGetSymbolAddress((void**)&b1p,   g_b1p);
    cudaGetSymbolAddress((void**)&w2ph,  g_w2ph);
    cudaGetSymbolAddress((void**)&rowtab, g_rowtab);

    cudaFuncSetAttribute(flash_k, cudaFuncAttributeMaxDynamicSharedMemorySize,
                         FLASH_SMEM_BYTES);
    cudaFuncSetAttribute(gemm_h, cudaFuncAttributeMaxDynamicSharedMemorySize,
                         GEMM_SMEM_BYTES);
    cudaFuncSetAttribute(gemm_ln_h, cudaFuncAttributeMaxDynamicSharedMemorySize,
                         LN_SMEM_BYTES);

    // 0. probe + conversions (mean zeroed inside prep_w_k)
    probe_k<<<1, 32>>>(rowtab);
    cvt4_k<<<(NB * SEQ * SEQ / 4 + 255) / 256, 256>>>((const float4*)HT,
                                                      (__half2*)hth, NB * SEQ * SEQ / 4);
    gather_h_k<<<TOKENS, 64>>>(hyper, emb, h0h);
    prep_w_k<<<(668160 + 255) / 256, 256>>>(Wg1, Wg2, Wqkv, Wo, Wff1, bff1, Wff2,
                                            wg1h, wg2h, wqkvh, woh, w1ph, b1p, w2ph,
                                            mean);

    // 1. t = h0 @ Wg1
    launch_gemm(h0h, wg1h, nullptr, th, TOKENS, HID, HID, HID, HID, HID,
                0, 0, 0, 1, 0);

    // 2. x = batched HT @ t + bg1
    launch_gemm(hth, th, bg1, xh, SEQ, HID, SEQ, SEQ, HID, HID,
                (long)SEQ * SEQ, (long)SEQ * HID, (long)SEQ * HID, NB, 0);

    // 3. t = x @ Wg2
    launch_gemm(xh, wg2h, nullptr, th, TOKENS, HID, HID, HID, HID, HID,
                0, 0, 0, 1, 0);

    // 4. x = batched HT @ t + bg2   (fp16 only; also the LN1 residual)
    launch_gemm(hth, th, bg2, xh, SEQ, HID, SEQ, SEQ, HID, HID,
                (long)SEQ * SEQ, (long)SEQ * HID, (long)SEQ * HID, NB, 0);

    // 5. qkv = x @ Wqkv + bqkv
    launch_gemm(xh, wqkvh, bqkv, qkvh, TOKENS, 3 * HID, HID,
                HID, 3 * HID, 3 * HID, 0, 0, 0, 1, 0);

    // 6. flash attention (single launch)
    flash_k<<<dim3(8, NB * NHEADS), 256, FLASH_SMEM_BYTES>>>(qkvh, ctxh, rowtab);

    // 7. x1 = LN1(x + ctx @ Wo + bo)   (fp16 residual, fp16 out)
    gemm_ln_h<<<TOKENS / 128, 256, LN_SMEM_BYTES>>>(ctxh, woh, bo, xh,
                                                    ln1g, ln1b, x1h, nullptr,
                                                    HID, HID);

    // 8. ff = relu(x1 @ w1p + b1p)
    launch_gemm(x1h, w1ph, b1p, ffh, TOKENS, FFP, HID, HID, FFP, FFP,
                0, 0, 0, 1, 1);

    // 9. LN2 + segment mean fused (fp16 residual, no gmem LN output)
    gemm_ln_h<<<TOKENS / 128, 256, LN_SMEM_BYTES>>>(ffh, w2ph, bff2, x1h,
                                                    ln2g, ln2b, nullptr,
                                                    mean, FFP, FFP);

    // 10. out = relu((p - n + f) @ fc1W + fc1b)
    final_k<<<NB, 256>>>(mean, fc1W, fc1b, (float*)d_out);
}